// round 7
// baseline (speedup 1.0000x reference)
#include <cuda_runtime.h>
#include <cstdint>

#define TT 512
#define BB 64
#define II 256
#define HH 512

// 64MB scratch for the precomputed input contribution xw[t][b][h]
__device__ float g_xw[TT * BB * HH];

// ---------------------------------------------------------------------------
// Phase 1: g_xw[m][h] = sum_i x[m][i] * W_ih[h][i] + b_ih[h] + b_hh[h]
// ---------------------------------------------------------------------------
__global__ __launch_bounds__(256) void phase1_kernel(
    const float* __restrict__ A,
    const float* __restrict__ W,
    const float* __restrict__ bih,
    const float* __restrict__ bhh)
{
    __shared__ float a_s[64][36];
    __shared__ float w_s[64][36];

    const int tid = threadIdx.x;
    const int m0 = blockIdx.x * 64;
    const int n0 = blockIdx.y * 64;
    const int r0 = (tid & 15) * 4;
    const int c0 = (tid >> 4) * 4;

    float acc[4][4] = {};

    for (int k0 = 0; k0 < II; k0 += 32) {
        #pragma unroll
        for (int i = 0; i < 2; i++) {
            int idx = tid + i * 256;
            int row = idx >> 3;
            int kc  = (idx & 7) * 4;
            *(float4*)&a_s[row][kc] = *(const float4*)&A[(m0 + row) * II + k0 + kc];
            *(float4*)&w_s[row][kc] = *(const float4*)&W[(n0 + row) * II + k0 + kc];
        }
        __syncthreads();

        #pragma unroll
        for (int kq = 0; kq < 8; kq++) {
            float4 av[4], wv[4];
            #pragma unroll
            for (int i = 0; i < 4; i++) av[i] = *(float4*)&a_s[r0 + i][kq * 4];
            #pragma unroll
            for (int j = 0; j < 4; j++) wv[j] = *(float4*)&w_s[c0 + j][kq * 4];
            #pragma unroll
            for (int i = 0; i < 4; i++) {
                #pragma unroll
                for (int j = 0; j < 4; j++) {
                    acc[i][j] += av[i].x * wv[j].x;
                    acc[i][j] += av[i].y * wv[j].y;
                    acc[i][j] += av[i].z * wv[j].z;
                    acc[i][j] += av[i].w * wv[j].w;
                }
            }
        }
        __syncthreads();
    }

    float b0 = bih[n0 + c0 + 0] + bhh[n0 + c0 + 0];
    float b1 = bih[n0 + c0 + 1] + bhh[n0 + c0 + 1];
    float b2 = bih[n0 + c0 + 2] + bhh[n0 + c0 + 2];
    float b3 = bih[n0 + c0 + 3] + bhh[n0 + c0 + 3];
    #pragma unroll
    for (int i = 0; i < 4; i++) {
        float4 o;
        o.x = acc[i][0] + b0;
        o.y = acc[i][1] + b1;
        o.z = acc[i][2] + b2;
        o.w = acc[i][3] + b3;
        *(float4*)&g_xw[(size_t)(m0 + r0 + i) * HH + n0 + c0] = o;
    }
}

// ---------------------------------------------------------------------------
// DSMEM / mbarrier helpers (cluster scope)
// ---------------------------------------------------------------------------
__device__ __forceinline__ uint32_t smem_u32(const void* p) {
    uint32_t a;
    asm("{ .reg .u64 t; cvta.to.shared.u64 t, %1; cvt.u32.u64 %0, t; }"
        : "=r"(a) : "l"(p));
    return a;
}

__device__ __forceinline__ void mbar_init(uint32_t mbar, uint32_t count) {
    asm volatile("mbarrier.init.shared.b64 [%0], %1;" :: "r"(mbar), "r"(count) : "memory");
}

// Wait with cluster-scope acquire (data arrives from peer CTAs' DSMEM stores).
__device__ __forceinline__ void mbar_wait_cluster(uint32_t mbar, uint32_t parity) {
    asm volatile(
        "{\n\t"
        ".reg .pred P;\n\t"
        "LW_%=:\n\t"
        "mbarrier.try_wait.parity.acquire.cluster.shared::cta.b64 P, [%0], %1, 0x989680;\n\t"
        "@P bra LD_%=;\n\t"
        "bra LW_%=;\n\t"
        "LD_%=:\n\t"
        "}"
        :: "r"(mbar), "r"(parity) : "memory");
}

// Release-arrive on the mbarrier at SMEM offset `mbar_local` in CTA `rank`.
// Release orders THIS thread's prior cluster-space stores.
__device__ __forceinline__ void mbar_arrive_remote(uint32_t mbar_local, uint32_t rank) {
    asm volatile(
        "{\n\t"
        ".reg .b32 ra;\n\t"
        "mapa.shared::cluster.u32 ra, %0, %1;\n\t"
        "mbarrier.arrive.release.cluster.shared::cluster.b64 _, [ra];\n\t"
        "}"
        :: "r"(mbar_local), "r"(rank) : "memory");
}

// 8-byte DSMEM store into CTA `rank` at the same SMEM offset as `laddr`.
__device__ __forceinline__ void dsmem_st_b64(uint32_t laddr, uint32_t rank, float a, float b) {
    uint64_t v = ((uint64_t)__float_as_uint(b) << 32) | (uint64_t)__float_as_uint(a);
    asm volatile(
        "{\n\t"
        ".reg .b32 ra;\n\t"
        "mapa.shared::cluster.u32 ra, %0, %1;\n\t"
        "st.shared::cluster.b64 [ra], %2;\n\t"
        "}"
        :: "r"(laddr), "r"(rank), "l"(v) : "memory");
}

// ---------------------------------------------------------------------------
// Phase 2: cluster scan, dataflow-pipelined.
//   16 clusters x 8 CTAs. Cluster cid owns batches [4*cid, 4*cid+4).
//   CTA rank r owns hidden rows [64r, 64r+64); W_hh slice (row-major) in SMEM.
//   Each thread owns ONE (h,b) output: full K=512 dot product, consumed in
//   8 chunks of 64 gated by per-source mbarriers (own chunk first -> waits
//   hit the already-complete fast path; no lockstep max-of-8 barrier).
//
// SMEM layout (floats, pad 4 per row for conflict-free banks):
//   [0, 33024)        w_s   [64][516]
//   [33024, 37152)    hbuf  [2][4][516]   (double-buffered h, [p][b][k])
//   [37152, 37424)    stage [4][68]       (this CTA's h slice, [b][h_l])
//   byte 149696:      mbarriers [2][8]    (parity x source rank, count=32)
// ---------------------------------------------------------------------------
#define SM_W     0
#define SM_HBUF  33024
#define SM_STAGE 37152
#define SM_MBAR_BYTES 149696
#define SM_TOTAL_BYTES (SM_MBAR_BYTES + 16 * 8)

__global__ void __cluster_dims__(8, 1, 1) __launch_bounds__(256, 1)
scan_kernel(const float* __restrict__ Whh, float* __restrict__ out, int has_hfinal)
{
    extern __shared__ float sm[];
    float* w_s   = sm + SM_W;
    float* hbuf  = sm + SM_HBUF;
    float* stage = sm + SM_STAGE;

    const uint32_t smem_base = smem_u32(sm);
    const uint32_t mbar_base = smem_base + SM_MBAR_BYTES;

    const int tid = threadIdx.x;
    uint32_t r;
    asm("mov.u32 %0, %%cluster_ctarank;" : "=r"(r));
    const int my_r = (int)r;
    const int cid = blockIdx.x >> 3;
    const int b0 = cid * 4;           // 4 batches per cluster
    const int h0 = my_r * 64;         // 64 hidden rows per CTA

    if (tid == 0) {
        #pragma unroll
        for (int i = 0; i < 16; i++) mbar_init(mbar_base + i * 8, 32);
    }

    // Load W_hh rows [h0, h0+64) row-major into w_s[h_l][k]. Coalesced.
    #pragma unroll
    for (int i = 0; i < 32; i++) {
        int idx = tid + i * 256;       // 0..8191 float4 ids
        int row = idx >> 7;            // 0..63
        int kq  = idx & 127;           // 0..127
        *(float4*)&w_s[row * 516 + kq * 4] =
            *(const float4*)&Whh[(size_t)(h0 + row) * HH + kq * 4];
    }
    __syncthreads();

    // All mbarriers initialized cluster-wide before any push/arrive.
    asm volatile("barrier.cluster.arrive.aligned;" ::: "memory");
    asm volatile("barrier.cluster.wait.aligned;" ::: "memory");

    // Compute role: warp covers 8 h x 4 b (w-LDS 128B/warp, h-LDS broadcast)
    const int h_l = (tid & 7) | ((tid >> 5) << 3);   // 0..63
    const int b_l = (tid >> 3) & 3;                  // 0..3
    const float* wrow = &w_s[h_l * 516];
    const size_t out_off_bh = (size_t)(b0 + b_l) * HH + (h0 + h_l);

    // Push role: 32 threads per destination rank
    const int p_dst = tid >> 5;            // 0..7 target rank
    const int p_b   = (tid >> 3) & 3;      // 0..3
    const int p_j   = (tid & 7) * 8;       // 0..56 (8 floats each)

    int ph[2] = {0, 0};

    for (int t = 0; t < TT; t++) {
        const int p = t & 1;

        // Prefetch xw before any waiting (latency hidden behind waits/compute)
        float xwv = g_xw[(size_t)t * (BB * HH) + out_off_bh];

        float ax = 0.f, ay = 0.f, az = 0.f, aw = 0.f;

        if (t > 0) {
            const float* hrow = &hbuf[(p * 4 + b_l) * 516];
            #pragma unroll
            for (int s = 0; s < 8; s++) {
                const int src = (my_r + s) & 7;
                mbar_wait_cluster(mbar_base + (p * 8 + src) * 8, (uint32_t)ph[p]);
                const float* wp = wrow + src * 64;
                const float* hp = hrow + src * 64;
                #pragma unroll
                for (int k4 = 0; k4 < 16; k4++) {
                    float4 wv = *(const float4*)(wp + k4 * 4);
                    float4 hv = *(const float4*)(hp + k4 * 4);
                    ax += wv.x * hv.x;
                    ay += wv.y * hv.y;
                    az += wv.z * hv.z;
                    aw += wv.w * hv.w;
                }
            }
            ph[p] ^= 1;
        }

        float v = fmaxf(xwv + (ax + ay) + (az + aw), 0.0f);

        // Stage my slice (for the push) and write the output
        stage[b_l * 68 + h_l] = v;
        out[(size_t)t * (BB * HH) + out_off_bh] = v;
        if (has_hfinal && t == TT - 1) {
            out[(size_t)TT * BB * HH + out_off_bh] = v;
        }
        __syncthreads();   // stage complete before anyone pushes it

        if (t < TT - 1) {
            const int pn = p ^ 1;
            // Push my 64h x 4b slice to all 8 ranks (incl. self):
            // thread handles 8 floats of batch p_b for destination p_dst.
            float4 v0 = *(const float4*)&stage[p_b * 68 + p_j];
            float4 v1 = *(const float4*)&stage[p_b * 68 + p_j + 4];
            uint32_t dst = smem_base +
                (uint32_t)(SM_HBUF + (pn * 4 + p_b) * 516 + my_r * 64 + p_j) * 4u;
            dsmem_st_b64(dst,      (uint32_t)p_dst, v0.x, v0.y);
            dsmem_st_b64(dst + 8,  (uint32_t)p_dst, v0.z, v0.w);
            dsmem_st_b64(dst + 16, (uint32_t)p_dst, v1.x, v1.y);
            dsmem_st_b64(dst + 24, (uint32_t)p_dst, v1.z, v1.w);
            // Release-arrive: orders THIS thread's stores; barrier fires after
            // all 32 pushing threads for this (dst, src=my_r) slice arrive.
            mbar_arrive_remote(mbar_base + (pn * 8 + my_r) * 8, (uint32_t)p_dst);
            __syncthreads();   // stage reusable next step only after all pushes read it
        }
    }

    // No CTA exits while peers' remote ops could still target its SMEM.
    asm volatile("barrier.cluster.arrive.aligned;" ::: "memory");
    asm volatile("barrier.cluster.wait.aligned;" ::: "memory");
}

// ---------------------------------------------------------------------------
extern "C" void kernel_launch(void* const* d_in, const int* in_sizes, int n_in,
                              void* d_out, int out_size) {
    const float* x   = (const float*)d_in[0];   // [T,B,I]
    const float* wih = (const float*)d_in[1];   // [H,I]
    const float* whh = (const float*)d_in[2];   // [H,H]
    const float* bih = (const float*)d_in[3];   // [H]
    const float* bhh = (const float*)d_in[4];   // [H]
    float* out = (float*)d_out;

    const int has_hfinal = (out_size >= TT * BB * HH + BB * HH) ? 1 : 0;

    cudaFuncSetAttribute(scan_kernel,
                         cudaFuncAttributeMaxDynamicSharedMemorySize,
                         SM_TOTAL_BYTES);

    dim3 g1(TT * BB / 64, HH / 64);   // (512, 8)
    phase1_kernel<<<g1, 256>>>(x, wih, bih, bhh);

    scan_kernel<<<128, 256, SM_TOTAL_BYTES>>>(whh, out, has_hfinal);
}

// round 8
// speedup vs baseline: 1.0215x; 1.0215x over previous
#include <cuda_runtime.h>
#include <cstdint>

#define TT 512
#define BB 64
#define II 256
#define HH 512

// 64MB scratch for the precomputed input contribution xw[t][b][h]
__device__ float g_xw[TT * BB * HH];

// ---------------------------------------------------------------------------
// Phase 1: g_xw[m][h] = sum_i x[m][i] * W_ih[h][i] + b_ih[h] + b_hh[h]
// ---------------------------------------------------------------------------
__global__ __launch_bounds__(256) void phase1_kernel(
    const float* __restrict__ A,
    const float* __restrict__ W,
    const float* __restrict__ bih,
    const float* __restrict__ bhh)
{
    __shared__ float a_s[64][36];
    __shared__ float w_s[64][36];

    const int tid = threadIdx.x;
    const int m0 = blockIdx.x * 64;
    const int n0 = blockIdx.y * 64;
    const int r0 = (tid & 15) * 4;
    const int c0 = (tid >> 4) * 4;

    float acc[4][4] = {};

    for (int k0 = 0; k0 < II; k0 += 32) {
        #pragma unroll
        for (int i = 0; i < 2; i++) {
            int idx = tid + i * 256;
            int row = idx >> 3;
            int kc  = (idx & 7) * 4;
            *(float4*)&a_s[row][kc] = *(const float4*)&A[(m0 + row) * II + k0 + kc];
            *(float4*)&w_s[row][kc] = *(const float4*)&W[(n0 + row) * II + k0 + kc];
        }
        __syncthreads();

        #pragma unroll
        for (int kq = 0; kq < 8; kq++) {
            float4 av[4], wv[4];
            #pragma unroll
            for (int i = 0; i < 4; i++) av[i] = *(float4*)&a_s[r0 + i][kq * 4];
            #pragma unroll
            for (int j = 0; j < 4; j++) wv[j] = *(float4*)&w_s[c0 + j][kq * 4];
            #pragma unroll
            for (int i = 0; i < 4; i++) {
                #pragma unroll
                for (int j = 0; j < 4; j++) {
                    acc[i][j] += av[i].x * wv[j].x;
                    acc[i][j] += av[i].y * wv[j].y;
                    acc[i][j] += av[i].z * wv[j].z;
                    acc[i][j] += av[i].w * wv[j].w;
                }
            }
        }
        __syncthreads();
    }

    float b0 = bih[n0 + c0 + 0] + bhh[n0 + c0 + 0];
    float b1 = bih[n0 + c0 + 1] + bhh[n0 + c0 + 1];
    float b2 = bih[n0 + c0 + 2] + bhh[n0 + c0 + 2];
    float b3 = bih[n0 + c0 + 3] + bhh[n0 + c0 + 3];
    #pragma unroll
    for (int i = 0; i < 4; i++) {
        float4 o;
        o.x = acc[i][0] + b0;
        o.y = acc[i][1] + b1;
        o.z = acc[i][2] + b2;
        o.w = acc[i][3] + b3;
        *(float4*)&g_xw[(size_t)(m0 + r0 + i) * HH + n0 + c0] = o;
    }
}

// ---------------------------------------------------------------------------
// DSMEM / mbarrier helpers (cluster scope)
// ---------------------------------------------------------------------------
__device__ __forceinline__ uint32_t smem_u32(const void* p) {
    uint32_t a;
    asm("{ .reg .u64 t; cvta.to.shared.u64 t, %1; cvt.u32.u64 %0, t; }"
        : "=r"(a) : "l"(p));
    return a;
}

__device__ __forceinline__ void mbar_init(uint32_t mbar, uint32_t count) {
    asm volatile("mbarrier.init.shared.b64 [%0], %1;" :: "r"(mbar), "r"(count) : "memory");
}

// Single per-step wait; cluster-scope acquire pairs with producers'
// release-arrives (data written into OUR smem by peer CTAs).
__device__ __forceinline__ void mbar_wait_cluster(uint32_t mbar, uint32_t parity) {
    asm volatile(
        "{\n\t"
        ".reg .pred P;\n\t"
        "LW_%=:\n\t"
        "mbarrier.try_wait.parity.acquire.cluster.shared::cta.b64 P, [%0], %1, 0x989680;\n\t"
        "@P bra LD_%=;\n\t"
        "bra LW_%=;\n\t"
        "LD_%=:\n\t"
        "}"
        :: "r"(mbar), "r"(parity) : "memory");
}

// Release-arrive on the mbarrier at SMEM offset `mbar_local` in CTA `rank`.
// Release orders THIS thread's prior cluster-space stores.
__device__ __forceinline__ void mbar_arrive_remote(uint32_t mbar_local, uint32_t rank) {
    asm volatile(
        "{\n\t"
        ".reg .b32 ra;\n\t"
        "mapa.shared::cluster.u32 ra, %0, %1;\n\t"
        "mbarrier.arrive.release.cluster.shared::cluster.b64 _, [ra];\n\t"
        "}"
        :: "r"(mbar_local), "r"(rank) : "memory");
}

// 8-byte DSMEM store into CTA `rank` at the same SMEM offset as `laddr`.
__device__ __forceinline__ void dsmem_st_b64(uint32_t laddr, uint32_t rank, float a, float b) {
    uint64_t v = ((uint64_t)__float_as_uint(b) << 32) | (uint64_t)__float_as_uint(a);
    asm volatile(
        "{\n\t"
        ".reg .b32 ra;\n\t"
        "mapa.shared::cluster.u32 ra, %0, %1;\n\t"
        "st.shared::cluster.b64 [ra], %2;\n\t"
        "}"
        :: "r"(laddr), "r"(rank), "l"(v) : "memory");
}

// ---------------------------------------------------------------------------
// Phase 2: cluster scan, lockstep with ONE acquire-wait per step.
//   16 clusters x 8 CTAs. Cluster cid owns batches [4*cid, 4*cid+4).
//   CTA rank r owns hidden rows [64r, 64r+64); W_hh slice row-major in SMEM.
//   Thread owns one (h,b): full K=512 dot product (FFMA-bound, 2048 cyc).
//   Exchange: warp w pushes the CTA's h-slice to rank w (4 b64/thread),
//   each thread does its OWN release-arrive (count 256 = 32 thr x 8 srcs).
//   Passing the next wait implies my own pushing warps finished reading
//   `stage`, so no post-push __syncthreads is needed (one sync per step).
//
// SMEM layout (floats, pad 4 per row):
//   [0, 33024)        w_s   [64][516]
//   [33024, 37152)    hbuf  [2][4][516]   (double-buffered h, [p][b][k])
//   [37152, 37424)    stage [4][68]       (this CTA's h slice, [b][h_l])
//   byte 149696:      mbarriers [2]       (parity, count=256)
// ---------------------------------------------------------------------------
#define SM_W     0
#define SM_HBUF  33024
#define SM_STAGE 37152
#define SM_MBAR_BYTES 149696
#define SM_TOTAL_BYTES (SM_MBAR_BYTES + 16)

__global__ void __cluster_dims__(8, 1, 1) __launch_bounds__(256, 1)
scan_kernel(const float* __restrict__ Whh, float* __restrict__ out, int has_hfinal)
{
    extern __shared__ float sm[];
    float* w_s   = sm + SM_W;
    float* hbuf  = sm + SM_HBUF;
    float* stage = sm + SM_STAGE;

    const uint32_t smem_base = smem_u32(sm);
    const uint32_t mbar0 = smem_base + SM_MBAR_BYTES;
    const uint32_t mbar1 = mbar0 + 8;

    const int tid = threadIdx.x;
    uint32_t r;
    asm("mov.u32 %0, %%cluster_ctarank;" : "=r"(r));
    const int my_r = (int)r;
    const int cid = blockIdx.x >> 3;
    const int b0 = cid * 4;           // 4 batches per cluster
    const int h0 = my_r * 64;         // 64 hidden rows per CTA

    if (tid == 0) {
        mbar_init(mbar0, 256);
        mbar_init(mbar1, 256);
    }

    // Load W_hh rows [h0, h0+64) row-major into w_s[h_l][k]. Coalesced.
    #pragma unroll
    for (int i = 0; i < 32; i++) {
        int idx = tid + i * 256;       // 0..8191 float4 ids
        int row = idx >> 7;            // 0..63
        int kq  = idx & 127;           // 0..127
        *(float4*)&w_s[row * 516 + kq * 4] =
            *(const float4*)&Whh[(size_t)(h0 + row) * HH + kq * 4];
    }
    __syncthreads();

    // All mbarriers initialized cluster-wide before any push/arrive.
    asm volatile("barrier.cluster.arrive.aligned;" ::: "memory");
    asm volatile("barrier.cluster.wait.aligned;" ::: "memory");

    // Compute role: warp covers 8 h x 4 b
    //   w-LDS.128: 8 distinct rows + 4-way bcast -> 128B, conflict-free
    //   h-LDS.128: 4 distinct rows + 8-way bcast -> 64B
    const int h_l = (tid & 7) | ((tid >> 5) << 3);   // 0..63
    const int b_l = (tid >> 3) & 3;                  // 0..3
    const float* wrow = &w_s[h_l * 516];
    const size_t out_off_bh = (size_t)(b0 + b_l) * HH + (h0 + h_l);

    // Push role: warp w -> destination rank w; lane handles 8 floats of one b.
    const int p_dst = tid >> 5;            // 0..7 target rank (per warp)
    const int p_b   = (tid >> 3) & 3;      // 0..3
    const int p_j   = (tid & 7) * 8;       // 0..56

    int ph0 = 0, ph1 = 0;

    // xw prefetch pipeline (one float per thread per step)
    float xw_cur = g_xw[out_off_bh];       // t = 0

    for (int t = 0; t < TT; t++) {
        const int p = t & 1;

        if (t > 0) {
            if (p == 0) { mbar_wait_cluster(mbar0, (uint32_t)ph0); ph0 ^= 1; }
            else        { mbar_wait_cluster(mbar1, (uint32_t)ph1); ph1 ^= 1; }
        }

        // Prefetch next step's xw immediately (overlaps with compute)
        float xw_next = 0.0f;
        if (t + 1 < TT) xw_next = g_xw[(size_t)(t + 1) * (BB * HH) + out_off_bh];

        float ax = 0.f, ay = 0.f, az = 0.f, aw = 0.f;
        if (t > 0) {
            const float* hrow = &hbuf[(p * 4 + b_l) * 516];
            #pragma unroll 16
            for (int k4 = 0; k4 < 128; k4++) {
                float4 wv = *(const float4*)(wrow + k4 * 4);
                float4 hv = *(const float4*)(hrow + k4 * 4);
                ax += wv.x * hv.x;
                ay += wv.y * hv.y;
                az += wv.z * hv.z;
                aw += wv.w * hv.w;
            }
        }

        float v = fmaxf(xw_cur + (ax + ay) + (az + aw), 0.0f);
        xw_cur = xw_next;

        stage[b_l * 68 + h_l] = v;
        __syncthreads();   // stage complete before pushes read it

        if (t < TT - 1) {
            const int pn = p ^ 1;
            // Push my 64h x 4b slice to rank p_dst (this warp's destination)
            float4 v0 = *(const float4*)&stage[p_b * 68 + p_j];
            float4 v1 = *(const float4*)&stage[p_b * 68 + p_j + 4];
            uint32_t dst = smem_base +
                (uint32_t)(SM_HBUF + (pn * 4 + p_b) * 516 + my_r * 64 + p_j) * 4u;
            dsmem_st_b64(dst,      (uint32_t)p_dst, v0.x, v0.y);
            dsmem_st_b64(dst + 8,  (uint32_t)p_dst, v0.z, v0.w);
            dsmem_st_b64(dst + 16, (uint32_t)p_dst, v1.x, v1.y);
            dsmem_st_b64(dst + 24, (uint32_t)p_dst, v1.z, v1.w);
            // Per-thread release-arrive: orders THIS thread's stores.
            // Barrier count 256 = 32 threads x 8 source CTAs.
            mbar_arrive_remote(pn == 0 ? mbar0 : mbar1, (uint32_t)p_dst);
        }

        // Off critical path: global output store
        out[(size_t)t * (BB * HH) + out_off_bh] = v;
        if (has_hfinal && t == TT - 1) {
            out[(size_t)TT * BB * HH + out_off_bh] = v;
        }
        // No trailing __syncthreads: passing the next wait requires my own
        // CTA's 32 arrives for parity pn, which happen only after those
        // threads finished reading `stage` -> safe to overwrite next step.
    }

    // No CTA exits while peers' remote ops could still target its SMEM.
    asm volatile("barrier.cluster.arrive.aligned;" ::: "memory");
    asm volatile("barrier.cluster.wait.aligned;" ::: "memory");
}

// ---------------------------------------------------------------------------
extern "C" void kernel_launch(void* const* d_in, const int* in_sizes, int n_in,
                              void* d_out, int out_size) {
    const float* x   = (const float*)d_in[0];   // [T,B,I]
    const float* wih = (const float*)d_in[1];   // [H,I]
    const float* whh = (const float*)d_in[2];   // [H,H]
    const float* bih = (const float*)d_in[3];   // [H]
    const float* bhh = (const float*)d_in[4];   // [H]
    float* out = (float*)d_out;

    const int has_hfinal = (out_size >= TT * BB * HH + BB * HH) ? 1 : 0;

    cudaFuncSetAttribute(scan_kernel,
                         cudaFuncAttributeMaxDynamicSharedMemorySize,
                         SM_TOTAL_BYTES);

    dim3 g1(TT * BB / 64, HH / 64);   // (512, 8)
    phase1_kernel<<<g1, 256>>>(x, wih, bih, bhh);

    scan_kernel<<<128, 256, SM_TOTAL_BYTES>>>(whh, out, has_hfinal);
}